// round 16
// baseline (speedup 1.0000x reference)
#include <cuda_runtime.h>
#include <stdint.h>
#include <math.h>

#define S    48
#define MD   10
#define H    48
#define NF   60

// dynamic smem layout (floats)
#define OFF_B    0                      // bias 48
#define OFF_LW   48
#define OFF_LB   96
#define OFF_C    144                    // 3 warps x 1600 (chunk bufs / partial exchange)
#define CWF      1600                   // 32 traj x 50 (5 rows x 10; float2 stride 25 odd)
#define OFF_F    (OFF_C + 3*CWF)        // 4944 : features 32 x 60
#define SMEM_FLOATS (OFF_F + 32*NF)     // 6864 floats = 27456 B -> 32KB granule -> 7 blocks/SM

__device__ __forceinline__ float fsqrt_fast(float x){ return x * rsqrtf(x); }

__global__ __launch_bounds__(96, 7)
void traj_fused(const float* __restrict__ coords, const int* __restrict__ lengths,
                const float* __restrict__ W, const float* __restrict__ bias,
                const float* __restrict__ ln_w, const float* __restrict__ ln_b,
                float* __restrict__ out, int B)
{
  extern __shared__ float sm[];
  int tid = threadIdx.x;

  // ---- stage params only (W stays in gmem/L1) ----
  if (tid < H){ sm[OFF_B+tid]=bias[tid]; sm[OFF_LW+tid]=ln_w[tid]; sm[OFF_LB+tid]=ln_b[tid]; }

  int r = tid >> 5, t = tid & 31;
  int base = blockIdx.x * 32;
  if (base >= B) return;
  int tmax = B - base; if (tmax > 32) tmax = 32;
  int b = base + t;
  bool act = (t < tmax);
  int n = act ? lengths[b] : 4;
  int m = n - 1, half = m >> 1;

  // 3-way row-split: warp r owns deltas [16r, 16r+16); rows staged [R0, R1]
  int kmin = r*16;
  int R0   = (r==0) ? 0 : r*16 - 1;
  int R1   = (r==2) ? 47 : r*16 + 16;
  int cosmin = (r==0) ? 1 : kmin;
  int ownlo = r*16, ownhi = r*16 + 16;

  float* cw  = sm + OFF_C + r*CWF;
  float* smF = sm + OFF_F;
  unsigned int cw_s = (unsigned int)__cvta_generic_to_shared(cw);

  float cur[MD], pd[MD], su[MD];
  float pinv = 0.f;
  float sc=0.f, scq=0.f, s_dm=0.f, s_dmsq=0.f, s_f=0.f, s_s=0.f, s_usq=0.f;
  float s_curv=0.f, s_curvsq=0.f, s_cos=0.f, s_neg=0.f;
  float mx_dm=-INFINITY, mx_curv=-INFINITY, nmn_curv=-INFINITY, nmn_cos=-INFINITY;
  #pragma unroll
  for (int j=0;j<MD;j++){ su[j]=0.f; pd[j]=0.f; cur[j]=0.f; }

  bool first = true;
  for (int c=0; c<4; c++){
    int c0  = R0 + c*5;
    int cnt = R1 - c0 + 1; if (cnt > 5) cnt = 5;    // 5,5,5,{2|3}
    int F2  = cnt*5;
    __syncwarp();
    // ---- cp.async staging: one LDGSTS per (traj, lane-slot) ----
    #pragma unroll 4
    for (int tt=0; tt<tmax; tt++){
      const float2* src = (const float2*)(coords + (size_t)(base+tt)*(S*MD) + c0*MD);
      if (t < F2){
        unsigned int dst = cw_s + (unsigned int)(tt*50 + 2*t)*4u;
        asm volatile("cp.async.ca.shared.global [%0], [%1], 8;\n"
                     :: "r"(dst), "l"(src + t) : "memory");
      }
    }
    asm volatile("cp.async.commit_group;\n" ::: "memory");
    asm volatile("cp.async.wait_group 0;\n" ::: "memory");
    __syncwarp();

    for (int ri=0; ri<cnt; ri++){
      int gi = c0 + ri;
      float nxt[MD];
      #pragma unroll
      for (int j2=0;j2<5;j2++){
        float2 p = *(const float2*)(cw + t*50 + ri*MD + 2*j2);
        nxt[2*j2]=p.x; nxt[2*j2+1]=p.y;
      }
      if (gi >= ownlo && gi < ownhi && gi < n){
        #pragma unroll
        for (int j=0;j<MD;j++){ sc += nxt[j]; scq = fmaf(nxt[j],nxt[j],scq); }
      }
      if (first){
        #pragma unroll
        for (int j=0;j<MD;j++) cur[j]=nxt[j];
        first = false;
        continue;
      }
      int k = gi - 1;
      float d[MD]; float dsq=0.f;
      #pragma unroll
      for (int j=0;j<MD;j++){ d[j]=nxt[j]-cur[j]; dsq=fmaf(d[j],d[j],dsq); }
      float rs   = rsqrtf(fmaxf(dsq,1e-30f));
      float dmag = (dsq>0.f) ? dsq*rs : 0.f;
      float inv  = __fdividef(1.f, fmaxf(dmag,1e-8f));
      bool kv = (k < m);

      if (k >= kmin && kv){
        s_dm += dmag; s_dmsq += dsq;
        if (k < half+1) s_f += dmag;
        if (k >= half)  s_s += dmag;
        mx_dm = fmaxf(mx_dm, dmag);
        #pragma unroll
        for (int j=0;j<MD;j++) su[j] = fmaf(d[j],inv,su[j]);
        s_usq = fmaf(dsq, inv*inv, s_usq);
      }
      if (k >= cosmin){
        float dot=0.f;
        #pragma unroll
        for (int j=0;j<MD;j++) dot = fmaf(pd[j], d[j], dot);
        float cs = dot*pinv*inv, cv = 1.f-cs;
        if (kv){
          s_curv += cv; s_curvsq = fmaf(cv,cv,s_curvsq);
          mx_curv = fmaxf(mx_curv, cv); nmn_curv = fmaxf(nmn_curv, -cv);
          s_cos += cs; nmn_cos = fmaxf(nmn_cos, -cs);
          if (cs < 0.f) s_neg += 1.f;
        }
        if (r==0 && k<=9)
          smF[t*NF + 51 + (k-1)] = kv ? cv : 0.f;
      }
      if (r==0 && k<3){
        #pragma unroll
        for (int j=0;j<MD;j++) smF[t*NF + 21 + k*MD + j] = d[j];
      }
      #pragma unroll
      for (int j=0;j<MD;j++){ pd[j]=d[j]; cur[j]=nxt[j]; }
      pinv = inv;
    }
  }

  // ---- partial exchange via dead chunk buffers (25 rows x 32) ----
  if (r > 0){
    float* p = sm + OFF_C + r*CWF;
    p[ 0*32+t]=sc;      p[ 1*32+t]=scq;     p[ 2*32+t]=s_dm;   p[ 3*32+t]=s_dmsq;
    p[ 4*32+t]=s_f;     p[ 5*32+t]=s_s;     p[ 6*32+t]=s_usq;  p[ 7*32+t]=s_curv;
    p[ 8*32+t]=s_curvsq;p[ 9*32+t]=s_cos;   p[10*32+t]=s_neg;
    p[11*32+t]=mx_dm;   p[12*32+t]=mx_curv; p[13*32+t]=nmn_curv; p[14*32+t]=nmn_cos;
    #pragma unroll
    for (int j=0;j<MD;j++) p[(15+j)*32+t]=su[j];
  }
  __syncthreads();

  if (r == 0){
    #pragma unroll
    for (int ww=1; ww<3; ww++){
      const float* p = sm + OFF_C + ww*CWF;
      sc      += p[ 0*32+t]; scq     += p[ 1*32+t];
      s_dm    += p[ 2*32+t]; s_dmsq  += p[ 3*32+t];
      s_f     += p[ 4*32+t]; s_s     += p[ 5*32+t];
      s_usq   += p[ 6*32+t]; s_curv  += p[ 7*32+t];
      s_curvsq+= p[ 8*32+t]; s_cos   += p[ 9*32+t];
      s_neg   += p[10*32+t];
      mx_dm    = fmaxf(mx_dm,   p[11*32+t]);
      mx_curv  = fmaxf(mx_curv, p[12*32+t]);
      nmn_curv = fmaxf(nmn_curv,p[13*32+t]);
      nmn_cos  = fmaxf(nmn_cos, p[14*32+t]);
      #pragma unroll
      for (int j=0;j<MD;j++) su[j]+=p[(15+j)*32+t];
    }

    // total displacement directly from gmem (L2-hot); b clamped for safety
    float tsq=0.f;
    {
      int bc = (b < B) ? b : (B-1);
      const float* cb = coords + (size_t)bc*(S*MD);
      int lo = (n-1)*MD;
      #pragma unroll
      for (int j=0;j<MD;j++){
        float diff = cb[lo+j] - cb[j];
        tsq = fmaf(diff,diff,tsq);
      }
    }

    float mf  = (float)m;
    float ncf = (float)(n-2);
    float cnt = (float)(n*MD);
    float rncf = __fdividef(1.f, ncf);

    float mean_coord = __fdividef(sc, cnt);
    float coord_var  = __fdividef(scq - cnt*mean_coord*mean_coord, cnt-1.f);
    float std_coord  = fsqrt_fast(fmaxf(coord_var,1e-30f));

    float mean_dm = __fdividef(s_dm, mf);
    float dm_var  = __fdividef(s_dmsq - mf*mean_dm*mean_dm, fmaxf(mf-1.f,1.f));
    float std_dm  = fsqrt_fast(fmaxf(dm_var,1e-30f));      // m>=3 always

    float mean_curv = s_curv * rncf;
    float curv_var  = __fdividef(s_curvsq - ncf*mean_curv*mean_curv, fmaxf(ncf-1.f,1.f));
    float std_curv  = (ncf>1.f) ? fsqrt_fast(fmaxf(curv_var,1e-30f)) : 0.f;

    float ssq=0.f;
    #pragma unroll
    for (int j=0;j<MD;j++) ssq = fmaf(su[j],su[j],ssq);
    float total_disp = (tsq>0.f) ? fsqrt_fast(fmaxf(tsq,1e-30f)) : 0.f;

    float npairs      = mf*(mf-1.f)*0.5f;
    float parallelism = 0.5f*(ssq - s_usq)*__fdividef(1.f, fmaxf(npairs,1.f));

    float rpl = __fdividef(1.f, s_dm+1e-9f);
    float disp_ratio  = total_disp * rpl;
    float loop_score  = 1.f - total_disp * rpl;
    float fh  = __fdividef(s_f, (float)(half+1));
    float sh2 = __fdividef(s_s, (float)(m-half));
    float rfh = __fdividef(1.f, fh+1e-9f);
    float convergence = (fh-sh2)*rfh;
    float cascade     = (sh2-fh)*rfh;
    float mean_cos    = s_cos * rncf;
    float dir_changes = s_neg * __fdividef(1.f, fmaxf(ncf,1.f));
    float jump        = (mean_dm>1e-9f) ? __fdividef(mx_dm, mean_dm) : 1.f;

    float* fr = smF + t*NF;
    fr[0]=total_disp;  fr[1]=s_dm;        fr[2]=disp_ratio;   fr[3]=(float)n*0.1f;
    fr[4]=mean_curv;   fr[5]=mx_curv;     fr[6]=std_curv;     fr[7]=mx_curv-(-nmn_curv);
    fr[8]=mean_cos;    fr[9]=-nmn_cos;    fr[10]=dir_changes; fr[11]=disp_ratio;
    fr[12]=loop_score; fr[13]=convergence;fr[14]=parallelism; fr[15]=jump;
    fr[16]=cascade;    fr[17]=mean_dm;    fr[18]=std_dm;      fr[19]=mean_coord;
    fr[20]=std_coord;
  }
  __syncthreads();

  // ---- GEMV: W from gmem (L1-hot); warp r handles trajectories [r*11, ...) ----
  int t0 = r*11;
  int NT = (r==2) ? 10 : 11;
  int tlo = t & 15;                        // clamp for upper-half loads
  float bb0 = sm[OFF_B + t];
  float bb1 = (t<16) ? sm[OFF_B + 32 + t] : 0.f;
  float lw0 = sm[OFF_LW + t], lb0 = sm[OFF_LB + t];
  float lw1 = (t<16) ? sm[OFF_LW + 32 + t] : 0.f;
  float lb1 = (t<16) ? sm[OFF_LB + 32 + t] : 0.f;

  float h0a[11], h1a[11];
  #pragma unroll
  for (int tt=0;tt<11;tt++){ h0a[tt]=bb0; h1a[tt]=bb1; }

  #pragma unroll
  for (int k4=0; k4<15; k4++){
    float w00 = __ldg(W + (4*k4+0)*H + t);
    float w01 = __ldg(W + (4*k4+1)*H + t);
    float w02 = __ldg(W + (4*k4+2)*H + t);
    float w03 = __ldg(W + (4*k4+3)*H + t);
    float w10 = __ldg(W + (4*k4+0)*H + 32 + tlo);
    float w11 = __ldg(W + (4*k4+1)*H + 32 + tlo);
    float w12 = __ldg(W + (4*k4+2)*H + 32 + tlo);
    float w13 = __ldg(W + (4*k4+3)*H + 32 + tlo);
    #pragma unroll
    for (int tt=0;tt<11;tt++){
      if (tt < NT){
        float4 fv = *(const float4*)(smF + (t0+tt)*NF + 4*k4);
        h0a[tt] = fmaf(fv.x,w00, fmaf(fv.y,w01, fmaf(fv.z,w02, fmaf(fv.w,w03, h0a[tt]))));
        h1a[tt] = fmaf(fv.x,w10, fmaf(fv.y,w11, fmaf(fv.z,w12, fmaf(fv.w,w13, h1a[tt]))));
      }
    }
  }

  #pragma unroll
  for (int tt=0;tt<11;tt++){
    if (tt >= NT) break;
    int bo = base + t0 + tt;
    float h0 = h0a[tt], h1 = h1a[tt];
    bool lo16 = (t<16);
    float ss = h0 + (lo16 ? h1 : 0.f);
    float sq = h0*h0 + (lo16 ? h1*h1 : 0.f);
    #pragma unroll
    for (int o=16;o;o>>=1){
      ss += __shfl_xor_sync(0xffffffffu, ss, o);
      sq += __shfl_xor_sync(0xffffffffu, sq, o);
    }
    float mu  = ss*(1.f/48.f);
    float var = sq*(1.f/48.f) - mu*mu;
    float iv  = rsqrtf(var+1e-5f);
    if (bo < B){
      float g0 = (h0-mu)*iv*lw0 + lb0;
      out[(size_t)bo*H + t] = 0.5f*g0*(1.f+erff(g0*0.70710678118654752f));
      if (lo16){
        float g1 = (h1-mu)*iv*lw1 + lb1;
        out[(size_t)bo*H + t+32] = 0.5f*g1*(1.f+erff(g1*0.70710678118654752f));
      }
    }
  }
}

extern "C" void kernel_launch(void* const* d_in, const int* in_sizes, int n_in,
                              void* d_out, int out_size) {
  const float* coords = (const float*)d_in[0];
  const int*   lengths= (const int*)  d_in[1];
  const float* W      = (const float*)d_in[2];
  const float* bias   = (const float*)d_in[3];
  const float* ln_w   = (const float*)d_in[4];
  const float* ln_b   = (const float*)d_in[5];
  float* out = (float*)d_out;
  int B = in_sizes[0] / (S*MD);

  size_t smem = (size_t)SMEM_FLOATS * sizeof(float);   // 27456 B
  cudaFuncSetAttribute(traj_fused, cudaFuncAttributeMaxDynamicSharedMemorySize, (int)smem);
  int grid = (B + 31) / 32;
  traj_fused<<<grid, 96, smem>>>(coords, lengths, W, bias, ln_w, ln_b, out, B);
}

// round 17
// speedup vs baseline: 1.1323x; 1.1323x over previous
#include <cuda_runtime.h>
#include <stdint.h>
#include <math.h>

#define S    48
#define MD   10
#define H    48
#define NF   60

// dynamic smem layout (floats) — identical to R15
#define OFF_B    0
#define OFF_LW   48
#define OFF_LB   96
#define OFF_C    144
#define CWF      1600                   // 32 traj x 50 (5 rows x 10; float2 stride 25 odd)
#define OFF_F    (OFF_C + 4*CWF)        // 6544
#define SMEM_FLOATS (OFF_F + 32*NF)     // 8464 floats = 33856 B

typedef unsigned long long u64;

__device__ __forceinline__ float fsqrt_fast(float x){ return x * rsqrtf(x); }
__device__ __forceinline__ u64 pk(float lo, float hi){
  u64 r; asm("mov.b64 %0, {%1,%2};" : "=l"(r) : "f"(lo), "f"(hi)); return r;
}
__device__ __forceinline__ void upk(float& lo, float& hi, u64 v){
  asm("mov.b64 {%0,%1}, %2;" : "=f"(lo), "=f"(hi) : "l"(v));
}
__device__ __forceinline__ u64 fma2(u64 a, u64 b, u64 c){
  u64 d; asm("fma.rn.f32x2 %0, %1, %2, %3;" : "=l"(d) : "l"(a), "l"(b), "l"(c)); return d;
}
__device__ __forceinline__ u64 add2(u64 a, u64 b){
  u64 d; asm("add.rn.f32x2 %0, %1, %2;" : "=l"(d) : "l"(a), "l"(b)); return d;
}
__device__ __forceinline__ u64 mul2(u64 a, u64 b){
  u64 d; asm("mul.rn.f32x2 %0, %1, %2;" : "=l"(d) : "l"(a), "l"(b)); return d;
}
__device__ __forceinline__ u64 lds64(unsigned int addr){
  u64 v; asm("ld.shared.b64 %0, [%1];" : "=l"(v) : "r"(addr)); return v;
}
#define NEG1_2 0xBF800000BF800000ull

__global__ __launch_bounds__(128, 5)
void traj_fused(const float* __restrict__ coords, const int* __restrict__ lengths,
                const float* __restrict__ W, const float* __restrict__ bias,
                const float* __restrict__ ln_w, const float* __restrict__ ln_b,
                float* __restrict__ out, int B)
{
  extern __shared__ float sm[];
  int tid = threadIdx.x;

  if (tid < H){ sm[OFF_B+tid]=bias[tid]; sm[OFF_LW+tid]=ln_w[tid]; sm[OFF_LB+tid]=ln_b[tid]; }

  int r = tid >> 5, t = tid & 31;
  int base = blockIdx.x * 32;
  if (base >= B) return;
  int tmax = B - base; if (tmax > 32) tmax = 32;
  int b = base + t;
  bool act = (t < tmax);
  int n = act ? lengths[b] : 4;
  int m = n - 1, half = m >> 1;

  int kmin = (r==0) ? 0 : r*12;
  int R0   = (r==0) ? 0 : r*12 - 1;
  int R1   = (r==3) ? 47 : (r+1)*12;
  int cosmin = (r==0) ? 1 : kmin;
  int ownlo = r*12, ownhi = r*12 + 12;

  float* cw  = sm + OFF_C + r*CWF;
  float* smF = sm + OFF_F;
  unsigned int cw_s   = (unsigned int)__cvta_generic_to_shared(cw);
  unsigned int row_s  = cw_s + (unsigned int)t*50u*4u;

  u64 cur2[5], pd2[5], su2[5];
  u64 sc2 = 0ull, scq2 = 0ull;
  float pinv = 0.f;
  float s_dm=0.f, s_dmsq=0.f, s_f=0.f, s_s=0.f, s_usq=0.f;
  float s_curv=0.f, s_curvsq=0.f, s_cos=0.f, s_neg=0.f;
  float mx_dm=-INFINITY, mx_curv=-INFINITY, nmn_curv=-INFINITY, nmn_cos=-INFINITY;
  #pragma unroll
  for (int j=0;j<5;j++){ su2[j]=0ull; pd2[j]=0ull; cur2[j]=0ull; }

  bool first = true;
  for (int c=0; c<3; c++){
    int c0  = R0 + c*5;
    int cnt = R1 - c0 + 1; if (cnt > 5) cnt = 5;
    int F2  = cnt*5;
    __syncwarp();
    #pragma unroll 4
    for (int tt=0; tt<tmax; tt++){
      const float2* src = (const float2*)(coords + (size_t)(base+tt)*(S*MD) + c0*MD);
      if (t < F2){
        unsigned int dst = cw_s + (unsigned int)(tt*50 + 2*t)*4u;
        asm volatile("cp.async.ca.shared.global [%0], [%1], 8;\n"
                     :: "r"(dst), "l"(src + t) : "memory");
      }
    }
    asm volatile("cp.async.commit_group;\n" ::: "memory");
    asm volatile("cp.async.wait_group 0;\n" ::: "memory");
    __syncwarp();

    for (int ri=0; ri<cnt; ri++){
      int gi = c0 + ri;
      u64 nxt2[5];
      #pragma unroll
      for (int j=0;j<5;j++) nxt2[j] = lds64(row_s + (unsigned int)(ri*MD + 2*j)*4u);

      if (gi >= ownlo && gi < ownhi && gi < n){
        #pragma unroll
        for (int j=0;j<5;j++){ sc2 = add2(sc2, nxt2[j]); scq2 = fma2(nxt2[j], nxt2[j], scq2); }
      }
      if (first){
        #pragma unroll
        for (int j=0;j<5;j++) cur2[j]=nxt2[j];
        first = false;
        continue;
      }
      int k = gi - 1;
      u64 d2[5];
      #pragma unroll
      for (int j=0;j<5;j++) d2[j] = fma2(cur2[j], NEG1_2, nxt2[j]);
      u64 q2 = mul2(d2[0], d2[0]);
      #pragma unroll
      for (int j=1;j<5;j++) q2 = fma2(d2[j], d2[j], q2);
      float qlo, qhi; upk(qlo, qhi, q2);
      float dsq = qlo + qhi;

      float rs   = rsqrtf(fmaxf(dsq,1e-30f));
      float dmag = (dsq>0.f) ? dsq*rs : 0.f;
      float inv  = __fdividef(1.f, fmaxf(dmag,1e-8f));
      bool kv = (k < m);

      if (k >= kmin && kv){
        s_dm += dmag; s_dmsq += dsq;
        if (k < half+1) s_f += dmag;
        if (k >= half)  s_s += dmag;
        mx_dm = fmaxf(mx_dm, dmag);
        u64 inv2 = pk(inv, inv);
        #pragma unroll
        for (int j=0;j<5;j++) su2[j] = fma2(d2[j], inv2, su2[j]);
        s_usq = fmaf(dsq, inv*inv, s_usq);
      }
      if (k >= cosmin){
        u64 o2 = mul2(pd2[0], d2[0]);
        #pragma unroll
        for (int j=1;j<5;j++) o2 = fma2(pd2[j], d2[j], o2);
        float olo, ohi; upk(olo, ohi, o2);
        float dot = olo + ohi;
        float cs = dot*pinv*inv, cv = 1.f-cs;
        if (kv){
          s_curv += cv; s_curvsq = fmaf(cv,cv,s_curvsq);
          mx_curv = fmaxf(mx_curv, cv); nmn_curv = fmaxf(nmn_curv, -cv);
          s_cos += cs; nmn_cos = fmaxf(nmn_cos, -cs);
          if (cs < 0.f) s_neg += 1.f;
        }
        if (r==0 && k<=9)
          smF[t*NF + 51 + (k-1)] = kv ? cv : 0.f;
      }
      if (r==0 && k<3){
        #pragma unroll
        for (int j=0;j<5;j++){
          float lo, hi; upk(lo, hi, d2[j]);
          smF[t*NF + 21 + k*MD + 2*j]   = lo;
          smF[t*NF + 21 + k*MD + 2*j+1] = hi;
        }
      }
      #pragma unroll
      for (int j=0;j<5;j++){ pd2[j]=d2[j]; cur2[j]=nxt2[j]; }
      pinv = inv;
    }
  }

  // unpack packed accumulators
  float su[MD];
  #pragma unroll
  for (int j=0;j<5;j++) upk(su[2*j], su[2*j+1], su2[j]);
  float sclo, schi, sqlo, sqhi;
  upk(sclo, schi, sc2); upk(sqlo, sqhi, scq2);
  float sc = sclo + schi, scq = sqlo + sqhi;

  // ---- partial exchange via dead chunk buffers ----
  if (r > 0){
    float* p = sm + OFF_C + r*CWF;
    p[ 0*32+t]=sc;      p[ 1*32+t]=scq;     p[ 2*32+t]=s_dm;   p[ 3*32+t]=s_dmsq;
    p[ 4*32+t]=s_f;     p[ 5*32+t]=s_s;     p[ 6*32+t]=s_usq;  p[ 7*32+t]=s_curv;
    p[ 8*32+t]=s_curvsq;p[ 9*32+t]=s_cos;   p[10*32+t]=s_neg;
    p[11*32+t]=mx_dm;   p[12*32+t]=mx_curv; p[13*32+t]=nmn_curv; p[14*32+t]=nmn_cos;
    #pragma unroll
    for (int j=0;j<MD;j++) p[(15+j)*32+t]=su[j];
  }
  __syncthreads();

  if (r == 0){
    #pragma unroll
    for (int ww=1; ww<4; ww++){
      const float* p = sm + OFF_C + ww*CWF;
      sc      += p[ 0*32+t]; scq     += p[ 1*32+t];
      s_dm    += p[ 2*32+t]; s_dmsq  += p[ 3*32+t];
      s_f     += p[ 4*32+t]; s_s     += p[ 5*32+t];
      s_usq   += p[ 6*32+t]; s_curv  += p[ 7*32+t];
      s_curvsq+= p[ 8*32+t]; s_cos   += p[ 9*32+t];
      s_neg   += p[10*32+t];
      mx_dm    = fmaxf(mx_dm,   p[11*32+t]);
      mx_curv  = fmaxf(mx_curv, p[12*32+t]);
      nmn_curv = fmaxf(nmn_curv,p[13*32+t]);
      nmn_cos  = fmaxf(nmn_cos, p[14*32+t]);
      #pragma unroll
      for (int j=0;j<MD;j++) su[j]+=p[(15+j)*32+t];
    }

    float tsq=0.f;
    {
      int bc = (b < B) ? b : (B-1);
      const float* cb = coords + (size_t)bc*(S*MD);
      int lo = (n-1)*MD;
      #pragma unroll
      for (int j=0;j<MD;j++){
        float diff = cb[lo+j] - cb[j];
        tsq = fmaf(diff,diff,tsq);
      }
    }

    float mf  = (float)m;
    float ncf = (float)(n-2);
    float cnt = (float)(n*MD);
    float rncf = __fdividef(1.f, ncf);

    float mean_coord = __fdividef(sc, cnt);
    float coord_var  = __fdividef(scq - cnt*mean_coord*mean_coord, cnt-1.f);
    float std_coord  = fsqrt_fast(fmaxf(coord_var,1e-30f));

    float mean_dm = __fdividef(s_dm, mf);
    float dm_var  = __fdividef(s_dmsq - mf*mean_dm*mean_dm, fmaxf(mf-1.f,1.f));
    float std_dm  = fsqrt_fast(fmaxf(dm_var,1e-30f));

    float mean_curv = s_curv * rncf;
    float curv_var  = __fdividef(s_curvsq - ncf*mean_curv*mean_curv, fmaxf(ncf-1.f,1.f));
    float std_curv  = (ncf>1.f) ? fsqrt_fast(fmaxf(curv_var,1e-30f)) : 0.f;

    float ssq=0.f;
    #pragma unroll
    for (int j=0;j<MD;j++) ssq = fmaf(su[j],su[j],ssq);
    float total_disp = (tsq>0.f) ? fsqrt_fast(fmaxf(tsq,1e-30f)) : 0.f;

    float npairs      = mf*(mf-1.f)*0.5f;
    float parallelism = 0.5f*(ssq - s_usq)*__fdividef(1.f, fmaxf(npairs,1.f));

    float rpl = __fdividef(1.f, s_dm+1e-9f);
    float disp_ratio  = total_disp * rpl;
    float loop_score  = 1.f - total_disp * rpl;
    float fh  = __fdividef(s_f, (float)(half+1));
    float sh2 = __fdividef(s_s, (float)(m-half));
    float rfh = __fdividef(1.f, fh+1e-9f);
    float convergence = (fh-sh2)*rfh;
    float cascade     = (sh2-fh)*rfh;
    float mean_cos    = s_cos * rncf;
    float dir_changes = s_neg * __fdividef(1.f, fmaxf(ncf,1.f));
    float jump        = (mean_dm>1e-9f) ? __fdividef(mx_dm, mean_dm) : 1.f;

    float* fr = smF + t*NF;
    fr[0]=total_disp;  fr[1]=s_dm;        fr[2]=disp_ratio;   fr[3]=(float)n*0.1f;
    fr[4]=mean_curv;   fr[5]=mx_curv;     fr[6]=std_curv;     fr[7]=mx_curv-(-nmn_curv);
    fr[8]=mean_cos;    fr[9]=-nmn_cos;    fr[10]=dir_changes; fr[11]=disp_ratio;
    fr[12]=loop_score; fr[13]=convergence;fr[14]=parallelism; fr[15]=jump;
    fr[16]=cascade;    fr[17]=mean_dm;    fr[18]=std_dm;      fr[19]=mean_coord;
    fr[20]=std_coord;
  }
  __syncthreads();

  // ---- GEMV: W from gmem (L1-hot), packed (h0,h1) f32x2 accumulators ----
  int t0 = r*8;
  int tlo = t & 15;
  float bb0 = sm[OFF_B + t];
  float bb1 = (t<16) ? sm[OFF_B + 32 + t] : 0.f;
  float lw0 = sm[OFF_LW + t], lb0 = sm[OFF_LB + t];
  float lw1 = (t<16) ? sm[OFF_LW + 32 + t] : 0.f;
  float lb1 = (t<16) ? sm[OFF_LB + 32 + t] : 0.f;

  u64 h01[8];
  #pragma unroll
  for (int tt=0;tt<8;tt++) h01[tt] = pk(bb0, bb1);

  #pragma unroll
  for (int k4=0; k4<15; k4++){
    float w00 = __ldg(W + (4*k4+0)*H + t);
    float w01 = __ldg(W + (4*k4+1)*H + t);
    float w02 = __ldg(W + (4*k4+2)*H + t);
    float w03 = __ldg(W + (4*k4+3)*H + t);
    float w10 = __ldg(W + (4*k4+0)*H + 32 + tlo);
    float w11 = __ldg(W + (4*k4+1)*H + 32 + tlo);
    float w12 = __ldg(W + (4*k4+2)*H + 32 + tlo);
    float w13 = __ldg(W + (4*k4+3)*H + 32 + tlo);
    u64 wp0 = pk(w00, w10), wp1 = pk(w01, w11), wp2 = pk(w02, w12), wp3 = pk(w03, w13);
    #pragma unroll
    for (int tt=0;tt<8;tt++){
      float4 fv = *(const float4*)(smF + (t0+tt)*NF + 4*k4);
      h01[tt] = fma2(pk(fv.x, fv.x), wp0, h01[tt]);
      h01[tt] = fma2(pk(fv.y, fv.y), wp1, h01[tt]);
      h01[tt] = fma2(pk(fv.z, fv.z), wp2, h01[tt]);
      h01[tt] = fma2(pk(fv.w, fv.w), wp3, h01[tt]);
    }
  }

  #pragma unroll
  for (int tt=0;tt<8;tt++){
    int bo = base + t0 + tt;
    float h0, h1; upk(h0, h1, h01[tt]);
    bool lo16 = (t<16);
    float ss = h0 + (lo16 ? h1 : 0.f);
    float sq = h0*h0 + (lo16 ? h1*h1 : 0.f);
    #pragma unroll
    for (int o=16;o;o>>=1){
      ss += __shfl_xor_sync(0xffffffffu, ss, o);
      sq += __shfl_xor_sync(0xffffffffu, sq, o);
    }
    float mu  = ss*(1.f/48.f);
    float var = sq*(1.f/48.f) - mu*mu;
    float iv  = rsqrtf(var+1e-5f);
    if (bo < B){
      float g0 = (h0-mu)*iv*lw0 + lb0;
      out[(size_t)bo*H + t] = 0.5f*g0*(1.f+erff(g0*0.70710678118654752f));
      if (lo16){
        float g1 = (h1-mu)*iv*lw1 + lb1;
        out[(size_t)bo*H + t+32] = 0.5f*g1*(1.f+erff(g1*0.70710678118654752f));
      }
    }
  }
}

extern "C" void kernel_launch(void* const* d_in, const int* in_sizes, int n_in,
                              void* d_out, int out_size) {
  const float* coords = (const float*)d_in[0];
  const int*   lengths= (const int*)  d_in[1];
  const float* W      = (const float*)d_in[2];
  const float* bias   = (const float*)d_in[3];
  const float* ln_w   = (const float*)d_in[4];
  const float* ln_b   = (const float*)d_in[5];
  float* out = (float*)d_out;
  int B = in_sizes[0] / (S*MD);

  size_t smem = (size_t)SMEM_FLOATS * sizeof(float);   // 33856 B
  cudaFuncSetAttribute(traj_fused, cudaFuncAttributeMaxDynamicSharedMemorySize, (int)smem);
  int grid = (B + 31) / 32;
  traj_fused<<<grid, 128, smem>>>(coords, lengths, W, bias, ln_w, ln_b, out, B);
}